// round 16
// baseline (speedup 1.0000x reference)
#include <cuda_runtime.h>
#include <cstdint>

// CostBuilder: stereo cost-volume construction.
// left, right: (B=4, C=32, H=64, W=128) fp32
// out:         (B, 2C=64, D=48, H, W) fp32
//   out[b, c,   d, h, w] = (w>=d) ? left [b,c,h,w]   : 0
//   out[b, C+c, d, h, w] = (w>=d) ? right[b,c,h,w-d] : 0
//
// R16: minimal-overhead right path. Evidence: DRAM% tracks store-issue rate
// (R13/14/15: issue 17.6/11.7/11.1 -> DRAM 73.6/71.7/69.1). Shuffle (R14)
// and staged-LDS (R15) both serialized the store stream. Here the right
// path reads shifted data DIRECTLY from gmem (inputs L2-resident): per pass
// 2 independent coalesced __ldg float4 (A/B straddle) + 4 stores with
// compile-time sub-shift assembly. No smem, no sync, no shuffle anywhere.

namespace {
constexpr int B   = 4;
constexpr int C   = 32;
constexpr int H   = 64;
constexpr int W   = 128;
constexpr int D   = 48;              // MAX_DISP / 4
constexpr int HW  = H * W;           // 8192
constexpr int TPB = 256;
constexpr int DPB = 4;               // d per block: k=d>>2 uniform, m=d&3 ct
constexpr int NDG = D / DPB;         // 12 d-groups
constexpr int PASSES = HW / 4 / TPB; // 8 float4 passes per plane
}

__global__ __launch_bounds__(TPB) void cost_builder_kernel(
    const float* __restrict__ left,
    const float* __restrict__ right,
    float* __restrict__ out)
{
    const int g    = blockIdx.x;
    const int dg   = g % NDG;            // d-group 0..11  (d = 4*dg + dd)
    const int bc2  = g / NDG;            // output channel-plane 0..255
    const int b    = bc2 >> 6;
    const int ch   = bc2 & 63;
    const bool is_right = ch >= C;
    const int c    = ch & (C - 1);

    const float* src = (is_right ? right : left) + (size_t)(b * C + c) * HW;
    const float4* src4 = reinterpret_cast<const float4*>(src);

    const int tid  = threadIdx.x;
    const int lane = tid & 31;
    const int w    = lane << 2;          // this lane's w within its row
    const int d0   = dg * DPB;

    const unsigned outbase0 = (unsigned)bc2 * D * HW;
    float4* outp[DPB];
    #pragma unroll
    for (int dd = 0; dd < DPB; ++dd)
        outp[dd] = reinterpret_cast<float4*>(out + outbase0 + (unsigned)(d0 + dd) * HW);

    if (!is_right) {
        // ---- LEFT PATH: d-invariant data, registers only ----
        #pragma unroll
        for (int p = 0; p < PASSES; ++p) {
            const int i = p * TPB + tid;
            const float4 lv = __ldg(src4 + i);
            #pragma unroll
            for (int dd = 0; dd < DPB; ++dd) {
                const int d = d0 + dd;
                float4 v;
                v.x = (w     >= d) ? lv.x : 0.0f;
                v.y = (w + 1 >= d) ? lv.y : 0.0f;
                v.z = (w + 2 >= d) ? lv.z : 0.0f;
                v.w = (w + 3 >= d) ? lv.w : 0.0f;
                __stcs(outp[dd] + i, v);
            }
        }
        return;
    }

    // ---- RIGHT PATH: direct-gmem shifted reads (L2-hit), no smem/sync ----
    // Value at w-d+j lives in float4 A = src4[row*32 + lane-k] (slots j>=m)
    // or B = src4[row*32 + lane-k-1] (slots j<m), k = dg, m = dd.
    // lane<k  => all 4 slots masked (w < d0 <= d).
    // lane==k => B slots masked (w+j = d0+j < d0+m = d). Clamp keeps the
    // speculative load in-plane.
    const int k = dg;
    const int ia0 = lane - k;
    const int iA = (ia0     < 0) ? 0 : ia0;       // clamped A index
    const int iB = (ia0 - 1 < 0) ? 0 : ia0 - 1;   // clamped B index

    #pragma unroll
    for (int p = 0; p < PASSES; ++p) {
        const int i = p * TPB + tid;               // warp = one row (i>>5)
        const int rowbase4 = (i >> 5) << 5;        // row * 32 float4s

        const float4 A  = __ldg(src4 + rowbase4 + iA);
        const float4 Bv = __ldg(src4 + rowbase4 + iB);

        // m = 0: A.x A.y A.z A.w
        {
            const int d = d0 + 0;
            float4 v;
            v.x = (w     >= d) ? A.x : 0.0f;
            v.y = (w + 1 >= d) ? A.y : 0.0f;
            v.z = (w + 2 >= d) ? A.z : 0.0f;
            v.w = (w + 3 >= d) ? A.w : 0.0f;
            __stcs(outp[0] + i, v);
        }
        // m = 1: B.w A.x A.y A.z
        {
            const int d = d0 + 1;
            float4 v;
            v.x = (w     >= d) ? Bv.w : 0.0f;
            v.y = (w + 1 >= d) ? A.x  : 0.0f;
            v.z = (w + 2 >= d) ? A.y  : 0.0f;
            v.w = (w + 3 >= d) ? A.z  : 0.0f;
            __stcs(outp[1] + i, v);
        }
        // m = 2: B.z B.w A.x A.y
        {
            const int d = d0 + 2;
            float4 v;
            v.x = (w     >= d) ? Bv.z : 0.0f;
            v.y = (w + 1 >= d) ? Bv.w : 0.0f;
            v.z = (w + 2 >= d) ? A.x  : 0.0f;
            v.w = (w + 3 >= d) ? A.y  : 0.0f;
            __stcs(outp[2] + i, v);
        }
        // m = 3: B.y B.z B.w A.x
        {
            const int d = d0 + 3;
            float4 v;
            v.x = (w     >= d) ? Bv.y : 0.0f;
            v.y = (w + 1 >= d) ? Bv.z : 0.0f;
            v.z = (w + 2 >= d) ? Bv.w : 0.0f;
            v.w = (w + 3 >= d) ? A.x  : 0.0f;
            __stcs(outp[3] + i, v);
        }
    }
}

extern "C" void kernel_launch(void* const* d_in, const int* in_sizes, int n_in,
                              void* d_out, int out_size)
{
    const float* left  = (const float*)d_in[0];
    const float* right = (const float*)d_in[1];
    float* out = (float*)d_out;

    const int grid = (2 * B * C) * NDG;   // 256 planes * 12 d-groups = 3072
    cost_builder_kernel<<<grid, TPB>>>(left, right, out);
}

// round 17
// speedup vs baseline: 1.0636x; 1.0636x over previous
#include <cuda_runtime.h>
#include <cstdint>

// CostBuilder: stereo cost-volume construction. CHAMPION (R13, reverted).
// left, right: (B=4, C=32, H=64, W=128) fp32
// out:         (B, 2C=64, D=48, H, W) fp32
//   out[b, c,   d, h, w] = (w>=d) ? left [b,c,h,w]   : 0
//   out[b, C+c, d, h, w] = (w>=d) ? right[b,c,h,w-d] : 0
//
// History: 16 rounds, 11 structural variants. Store-bound kernel; DRAM
// active is paced by store-issue cadence. This config is the measured
// optimum: bench 57.9us, ncu 60.3us, DRAM 73.6%, HBM 5.83 TB/s.
// Attempts to push further (DPB=4 with shuffle / staged-LDS / direct-gmem
// shifted reads, R14-R16) all serialized the store stream (issue 17.6% ->
// ~11.5%) and regressed to 62-64us. Reverted and held.
//
// Config: one block = (channel-plane, 3 consecutive d), grid 4096.
// Left planes are d-invariant: registers only, no smem, no sync.
// Right planes: plane staged once in bank-swizzled shared, conflict-free
// shifted LDS. __stcs evict-first STG.128 stores throughout.

namespace {
constexpr int B   = 4;
constexpr int C   = 32;
constexpr int H   = 64;
constexpr int W   = 128;
constexpr int D   = 48;              // MAX_DISP / 4
constexpr int HW  = H * W;           // 8192
constexpr int TPB = 256;
constexpr int DPB = 3;               // d values per block
constexpr int NDG = D / DPB;         // 16 d-groups
constexpr int PASSES = HW / 4 / TPB; // 8 float4 passes per plane

// Per-row bank swizzle: pos(w) = (w%4)*32 + w/4. For lane-parallel access at
// w = 4*lane + e, idx>>2 = lane + const -> consecutive banks, conflict-free.
__device__ __forceinline__ int swz(int w) { return ((w & 3) << 5) | (w >> 2); }
}

__global__ __launch_bounds__(TPB) void cost_builder_kernel(
    const float* __restrict__ left,
    const float* __restrict__ right,
    float* __restrict__ out)
{
    const int g    = blockIdx.x;
    const int dg   = g & (NDG - 1);      // d-group 0..15
    const int bc2  = g >> 4;             // output channel-plane 0..255
    const int b    = bc2 >> 6;
    const int ch   = bc2 & 63;
    const bool is_right = ch >= C;
    const int c    = ch & (C - 1);

    const float* src = (is_right ? right : left) + (size_t)(b * C + c) * HW;

    __shared__ float s[HW];              // 32KB plane (right path only)

    const int tid  = threadIdx.x;
    const int lane = tid & 31;
    const int w    = lane << 2;          // this lane's w within its row
    const int d0   = dg * DPB;

    const unsigned outbase0 = (unsigned)bc2 * D * HW;

    if (!is_right) {
        // ---- LEFT PATH: d-invariant data, registers only, no smem/sync ----
        #pragma unroll
        for (int p = 0; p < PASSES; ++p) {
            const int i = p * TPB + tid;
            const float4 lv = reinterpret_cast<const float4*>(src)[i];

            #pragma unroll
            for (int dd = 0; dd < DPB; ++dd) {
                const int d = d0 + dd;
                float4 v;
                v.x = (w     >= d) ? lv.x : 0.0f;
                v.y = (w + 1 >= d) ? lv.y : 0.0f;
                v.z = (w + 2 >= d) ? lv.z : 0.0f;
                v.w = (w + 3 >= d) ? lv.w : 0.0f;
                __stcs(reinterpret_cast<float4*>(out + outbase0 + (unsigned)d * HW) + i, v);
            }
        }
        return;
    }

    // ---- RIGHT PATH: swizzled smem, shifted conflict-free reads ----
    #pragma unroll
    for (int p = 0; p < PASSES; ++p) {
        const int i = p * TPB + tid;
        const float4 v = reinterpret_cast<const float4*>(src)[i];
        const int rowbase = (i >> 5) * W;
        s[rowbase +  0 + lane] = v.x;
        s[rowbase + 32 + lane] = v.y;
        s[rowbase + 64 + lane] = v.z;
        s[rowbase + 96 + lane] = v.w;
    }
    __syncthreads();

    #pragma unroll
    for (int dd = 0; dd < DPB; ++dd) {
        const int d = d0 + dd;
        float4* outp = reinterpret_cast<float4*>(out + outbase0 + (unsigned)d * HW);

        #pragma unroll
        for (int p = 0; p < PASSES; ++p) {
            const int i = p * TPB + tid;
            const int rowbase = (i >> 5) * W;
            const int q0 = w - d;

            float4 v;
            // max(q,0) keeps speculative LDS in-bounds; mask zeroes w<d.
            v.x = (w     >= d) ? s[rowbase + swz(q0     < 0 ? 0 : q0    )] : 0.0f;
            v.y = (w + 1 >= d) ? s[rowbase + swz(q0 + 1 < 0 ? 0 : q0 + 1)] : 0.0f;
            v.z = (w + 2 >= d) ? s[rowbase + swz(q0 + 2 < 0 ? 0 : q0 + 2)] : 0.0f;
            v.w = (w + 3 >= d) ? s[rowbase + swz(q0 + 3 < 0 ? 0 : q0 + 3)] : 0.0f;

            __stcs(outp + i, v);                 // streaming store, evict-first
        }
    }
}

extern "C" void kernel_launch(void* const* d_in, const int* in_sizes, int n_in,
                              void* d_out, int out_size)
{
    const float* left  = (const float*)d_in[0];
    const float* right = (const float*)d_in[1];
    float* out = (float*)d_out;

    const int grid = (2 * B * C) * NDG;   // 256 planes * 16 d-groups = 4096
    cost_builder_kernel<<<grid, TPB>>>(left, right, out);
}